// round 14
// baseline (speedup 1.0000x reference)
#include <cuda_runtime.h>
#include <cuda_fp16.h>
#include <cstdint>

// ---------------------------------------------------------------------------
// Sparse2x4Conv2d via shift-GEMM on mma.sync fp16 hi/lo (fp32 accum).
//   conv3x3 = sum over 9 taps of GEMM: y[oc][px] += Wtap[oc][c] * x[px+D][c]
// R13: 3-stage cp.async pipeline (prefetch distance 2) to hide smem-fill
// latency behind MMA; 207KB smem, 1 CTA/SM.
//   A*B ~= Ah*Bh + Ah*Bl + Al*Bh   (residual ~2^-23)
// ---------------------------------------------------------------------------

#define HW      56
#define PIX     3136
#define GROUPS  2
#define CG      128
#define OCG     128
#define INF     1152
#define QN      73728
#define NCHUNK  18          // 9 taps x 2 channel-halves of 64
#define NT      112         // N tile: 2 output rows
#define AP      72          // k-row stride in halves (144B) -> conflict-free ldsm

// per-stage smem byte offsets
#define SO_AHI   0                       // 128 x 144
#define SO_ALO   18432
#define SO_BHI   36864                   // 112 x 144
#define SO_BLO   52992
#define STG_B    69120
#define NSTAGE   3
#define SMEM_TOTAL (STG_B * NSTAGE)      // 207360

// pre-split weights, tap-major: [g][chunk][oc=128][c=64] fp16
__device__ __align__(16) __half g_Whi[(size_t)GROUPS * NCHUNK * 128 * 64];
__device__ __align__(16) __half g_Wlo[(size_t)GROUPS * NCHUNK * 128 * 64];
// transposed input: [bg=64][px=3136][c=128] fp16 hi/lo
__device__ __align__(16) __half g_xThi[(size_t)64 * PIX * 128];
__device__ __align__(16) __half g_xTlo[(size_t)64 * PIX * 128];

static __device__ __forceinline__ uint32_t smem_u32(const void* p) {
    return (uint32_t)__cvta_generic_to_shared(p);
}
static __device__ __forceinline__ void cp16(uint32_t dst, const __half* src, int sz) {
    asm volatile("cp.async.cg.shared.global [%0], [%1], 16, %2;"
                 :: "r"(dst), "l"(src), "r"(sz) : "memory");
}
static __device__ __forceinline__ void ldsm_x4(uint32_t* r, uint32_t a) {
    asm volatile("ldmatrix.sync.aligned.m8n8.x4.shared.b16 {%0,%1,%2,%3}, [%4];"
                 : "=r"(r[0]), "=r"(r[1]), "=r"(r[2]), "=r"(r[3]) : "r"(a));
}
static __device__ __forceinline__ void ldsm_x2(uint32_t* r, uint32_t a) {
    asm volatile("ldmatrix.sync.aligned.m8n8.x2.shared.b16 {%0,%1}, [%2];"
                 : "=r"(r[0]), "=r"(r[1]) : "r"(a));
}
static __device__ __forceinline__ void mma16816(float* c, const uint32_t* a,
                                                const uint32_t* b) {
    asm volatile(
        "mma.sync.aligned.m16n8k16.row.col.f32.f16.f16.f32 "
        "{%0,%1,%2,%3}, {%4,%5,%6,%7}, {%8,%9}, {%0,%1,%2,%3};"
        : "+f"(c[0]), "+f"(c[1]), "+f"(c[2]), "+f"(c[3])
        : "r"(a[0]), "r"(a[1]), "r"(a[2]), "r"(a[3]), "r"(b[0]), "r"(b[1]));
}

// ---------------------------------------------------------------------------
// Kernel 0: transpose x [bg][c][px] fp32 -> xT [bg][px][c] fp16 hi/lo.
// ---------------------------------------------------------------------------
__global__ __launch_bounds__(256)
void xt_kernel(const float* __restrict__ x) {
    __shared__ float s[128][33];
    const int tid = threadIdx.x;
    const int bg  = blockIdx.y;
    const int px0 = blockIdx.x * 32;
    const float* xb = x + (size_t)bg * 128 * PIX;

#pragma unroll
    for (int i = 0; i < 16; i++) {
        int idx = tid + i * 256;
        int c = idx >> 5, p = idx & 31;
        s[c][p] = xb[(size_t)c * PIX + px0 + p];
    }
    __syncthreads();
#pragma unroll
    for (int i = 0; i < 8; i++) {
        int idx = tid + i * 256;         // 0..2047
        int p  = idx >> 6;               // 0..31
        int c2 = (idx & 63) * 2;         // even channel
        float v0 = s[c2][p], v1 = s[c2 + 1][p];
        __half h0 = __float2half_rn(v0);
        __half h1 = __float2half_rn(v1);
        __half l0 = __float2half_rn(v0 - __half2float(h0));
        __half l1 = __float2half_rn(v1 - __half2float(h1));
        uint32_t hp = ((uint32_t)__half_as_ushort(h1) << 16) | __half_as_ushort(h0);
        uint32_t lp = ((uint32_t)__half_as_ushort(l1) << 16) | __half_as_ushort(l0);
        size_t o = ((size_t)bg * PIX + px0 + p) * 128 + c2;
        *reinterpret_cast<uint32_t*>(&g_xThi[o]) = hp;
        *reinterpret_cast<uint32_t*>(&g_xTlo[o]) = lp;
    }
}

// ---------------------------------------------------------------------------
// Kernel 1: argmax-masked weights -> fp16 hi/lo, tap-major GEMM layout.
// ---------------------------------------------------------------------------
__global__ void mask_split_kernel(const float* __restrict__ Ws,
                                  const float* __restrict__ cw,
                                  const float* __restrict__ gb,
                                  const float* __restrict__ mp) {
    int q = blockIdx.x * blockDim.x + threadIdx.x;
    if (q >= QN) return;

    float best = cw[q * 6 + 0] + gb[q * 6 + 0];
    int idx = 0;
#pragma unroll
    for (int j = 1; j < 6; j++) {
        float v = cw[q * 6 + j] + gb[q * 6 + j];
        if (v > best) { best = v; idx = j; }
    }
    const float4 m  = *reinterpret_cast<const float4*>(mp + idx * 4);
    const float4 w4 = *reinterpret_cast<const float4*>(Ws + q * 4);
    float wm[4] = { w4.x * m.x, w4.y * m.y, w4.z * m.z, w4.w * m.w };

    int e0  = q * 4;
    int g   = e0 / (OCG * INF);
    int rem = e0 % (OCG * INF);
    int oc  = rem / INF;
    int i0  = rem % INF;

#pragma unroll
    for (int k = 0; k < 4; k++) {
        int i = i0 + k;
        int c = i / 9;
        int t = i - c * 9;
        int chunk = t * 2 + (c >> 6);
        int col   = c & 63;
        __half hb = __float2half_rn(wm[k]);
        __half lb = __float2half_rn(wm[k] - __half2float(hb));
        size_t o = (((size_t)(g * NCHUNK) + chunk) * 128 + oc) * 64 + col;
        g_Whi[o] = hb;
        g_Wlo[o] = lb;
    }
}

// ---------------------------------------------------------------------------
// Kernel 2: per-CTA 128(oc) x 112(px), 18 chunks, 3-stage cp.async pipeline.
// ---------------------------------------------------------------------------
struct PfCtx {
    uint32_t smb;
    const __half *wh_g, *wl_g, *xh, *xl;
    int h0img, seg, rid;
    int hhB[4], wwB[4];
};

static __device__ __forceinline__ void prefetch_chunk(const PfCtx& P, int chunk,
                                                      int stg) {
    const uint32_t sb = P.smb + stg * STG_B;
    const int t     = chunk >> 1;
    const int chalf = chunk & 1;
    const int kh = t / 3, kw = t - kh * 3;

    const __half* wh = P.wh_g + (size_t)chunk * 128 * 64;
    const __half* wl = P.wl_g + (size_t)chunk * 128 * 64;
#pragma unroll
    for (int i = 0; i < 4; i++) {
        int r = P.rid + 32 * i;
        cp16(sb + SO_AHI + r * 144 + P.seg * 16, wh + r * 64 + P.seg * 8, 16);
        cp16(sb + SO_ALO + r * 144 + P.seg * 16, wl + r * 64 + P.seg * 8, 16);
    }
#pragma unroll
    for (int i = 0; i < 4; i++) {
        int r = P.rid + 32 * i;
        if (r < NT) {
            int hp = P.h0img + P.hhB[i] + kh - 1;
            int wp = P.wwB[i] + kw - 1;
            bool ok = ((unsigned)hp < HW) & ((unsigned)wp < HW);
            size_t po = ok ? ((size_t)(hp * HW + wp) * 128 + chalf * 64) : 0;
            int sz = ok ? 16 : 0;
            cp16(sb + SO_BHI + r * 144 + P.seg * 16, P.xh + po + P.seg * 8, sz);
            cp16(sb + SO_BLO + r * 144 + P.seg * 16, P.xl + po + P.seg * 8, sz);
        }
    }
}

__global__ __launch_bounds__(256)
void conv_mma_kernel(const float* __restrict__ x, float* __restrict__ out) {
    extern __shared__ __align__(128) uint8_t sm[];

    const int tid  = threadIdx.x;
    const int wid  = tid >> 5;
    const int lane = tid & 31;

    const int tile  = blockIdx.x;         // 0..27 (2 output rows)
    const int bz    = blockIdx.y;
    const int b     = bz >> 1;
    const int g     = bz & 1;

    // warp tile position: 4 (m) x 2 (n)
    const int m0 = (wid & 3) * 32;
    const int n0 = (wid >> 2) * 56;
    const int aoff = (m0 + (lane & 15)) * (AP * 2) + (lane >> 4) * 16;
    const int boff = (n0 + (lane & 7)) * (AP * 2) + ((lane >> 3) & 1) * 16;

    PfCtx P;
    P.smb   = smem_u32(sm);
    P.wh_g  = g_Whi + (size_t)g * NCHUNK * 128 * 64;
    P.wl_g  = g_Wlo + (size_t)g * NCHUNK * 128 * 64;
    P.xh    = g_xThi + (size_t)bz * PIX * 128;
    P.xl    = g_xTlo + (size_t)bz * PIX * 128;
    P.h0img = tile * 2;
    P.seg   = tid & 7;
    P.rid   = tid >> 3;
#pragma unroll
    for (int i = 0; i < 4; i++) {
        int r = P.rid + 32 * i;
        P.hhB[i] = (r >= 56);
        P.wwB[i] = r - P.hhB[i] * 56;
    }

    float c[2][7][4];
#pragma unroll
    for (int i = 0; i < 2; i++)
#pragma unroll
        for (int j = 0; j < 7; j++)
#pragma unroll
            for (int k = 0; k < 4; k++) c[i][j][k] = 0.0f;

    // preload chunks 0,1 into stages 0,1
    prefetch_chunk(P, 0, 0);
    asm volatile("cp.async.commit_group;" ::: "memory");
    prefetch_chunk(P, 1, 1);
    asm volatile("cp.async.commit_group;" ::: "memory");

    for (int chunk = 0; chunk < NCHUNK; chunk++) {
        __syncthreads();                  // compute(chunk-1) fully done

        // prefetch chunk+2 into the stage freed by compute(chunk-1)
        if (chunk + 2 < NCHUNK)
            prefetch_chunk(P, chunk + 2, (chunk + 2) % NSTAGE);
        asm volatile("cp.async.commit_group;" ::: "memory");  // always commit

        asm volatile("cp.async.wait_group 2;" ::: "memory");  // chunk's data done
        __syncthreads();

        const uint32_t sb = P.smb + (chunk % NSTAGE) * STG_B;
#pragma unroll
        for (int ks = 0; ks < 4; ks++) {
            const int kb = ks * 32;
            uint32_t ah[2][4], al[2][4];
            ldsm_x4(ah[0], sb + SO_AHI + aoff + kb);
            ldsm_x4(ah[1], sb + SO_AHI + aoff + kb + 16 * AP * 2);
            ldsm_x4(al[0], sb + SO_ALO + aoff + kb);
            ldsm_x4(al[1], sb + SO_ALO + aoff + kb + 16 * AP * 2);
#pragma unroll
            for (int nt = 0; nt < 7; nt++) {
                uint32_t bh[2], bl[2];
                ldsm_x2(bh, sb + SO_BHI + boff + kb + nt * (8 * AP * 2));
                ldsm_x2(bl, sb + SO_BLO + boff + kb + nt * (8 * AP * 2));
                mma16816(c[0][nt], ah[0], bh);
                mma16816(c[1][nt], ah[1], bh);
                mma16816(c[0][nt], ah[0], bl);
                mma16816(c[1][nt], ah[1], bl);
                mma16816(c[0][nt], al[0], bh);
                mma16816(c[1][nt], al[1], bh);
            }
        }
    }

    // ---- epilogue: direct STG, lane-quads write full 32B sectors ----
    const size_t obase = (size_t)(b * 256 + g * 128) * PIX + (size_t)tile * NT;
    const int r0 = m0 + (lane >> 2);
    const int nn = n0 + 2 * (lane & 3);
#pragma unroll
    for (int mt = 0; mt < 2; mt++) {
#pragma unroll
        for (int nt = 0; nt < 7; nt++) {
            const int r = r0 + mt * 16;
            const int n = nn + nt * 8;
            *reinterpret_cast<float2*>(out + obase + (size_t)r * PIX + n) =
                make_float2(c[mt][nt][0], c[mt][nt][1]);
            *reinterpret_cast<float2*>(out + obase + (size_t)(r + 8) * PIX + n) =
                make_float2(c[mt][nt][2], c[mt][nt][3]);
        }
    }
}

// ---------------------------------------------------------------------------
// inputs: x, Ws, choice_weights, gumbels, masking_patterns
// ---------------------------------------------------------------------------
extern "C" void kernel_launch(void* const* d_in, const int* in_sizes, int n_in,
                              void* d_out, int out_size) {
    const float* x  = (const float*)d_in[0];
    const float* Ws = (const float*)d_in[1];
    const float* cw = (const float*)d_in[2];
    const float* gb = (const float*)d_in[3];
    const float* mp = (const float*)d_in[4];
    float* out = (float*)d_out;

    cudaFuncSetAttribute(conv_mma_kernel,
                         cudaFuncAttributeMaxDynamicSharedMemorySize, SMEM_TOTAL);

    dim3 tgrid(PIX / 32, 64);
    xt_kernel<<<tgrid, 256>>>(x);
    mask_split_kernel<<<(QN + 255) / 256, 256>>>(Ws, cw, gb, mp);

    dim3 grid(28, 64);     // spatial tiles x (b,g)
    conv_mma_kernel<<<grid, 256, SMEM_TOTAL>>>(x, out);
}